// round 11
// baseline (speedup 1.0000x reference)
#include <cuda_runtime.h>
#include <math.h>

// Problem constants (fixed shapes from setup_inputs)
#define LL 4
#define BB 8
#define NS 1200
#define NL 128
#define CC 768
#define HH 448
#define WW 448
#define GS 56            // H/8   (grid cols, small)
#define GL 16            // H/28  (grid cols, large)
#define VS (GS*GS)       // 3136
#define VL (GL*GL)       // 256
#define LB (LL*BB)       // 32
#define ROWS_PER_BLK 16          // 8 warps x 2 rows (R9 config, best k_dist)
#define NBS (NS/ROWS_PER_BLK)    // 75
#define NBL (NL/ROWS_PER_BLK)    // 8
#define GDX (NBS+NBL)            // 83
#define BAND (GDX*BB)            // 664 blocks per l
#define NSAMP (BB*VS + BB*VL)    // 27136 mask samples
#define SAMP_PER_BLK 41          // ceil(27136/664) per l-band block
#define NGB (2*LB)               // 64 stats groups

// Scratch (no allocations -> __device__ globals). Device-code refs only.
// Zero-initialized at load; counters reset by the finalize block each call.
__device__ float g_dist_s[LB*NS];
__device__ float g_dist_l[LB*NL];
__device__ unsigned char g_nz_s[LL*NS*8];   // [l][n][b] nonzero flags
__device__ unsigned char g_nz_l[LL*NL*8];
__device__ unsigned char g_valid_s[BB*VS];
__device__ unsigned char g_valid_l[BB*VL];
__device__ float g_sp[NGB];
__device__ float g_sn[NGB];
__device__ int   g_cp[NGB];
__device__ int   g_cn[NGB];
__device__ unsigned g_cnt[LL];   // per-l completion tickets
__device__ unsigned g_done2;     // stats-block completion counter

// ---------------------------------------------------------------------------
// Single fused kernel.
// Phase 1 (all blocks): distance rows + per-l-band f_k mask sampling.
// Phase 2 (last 16 ticket holders of each l band): per-gb masked accumulation,
//         overlapped with other bands' phase-1 work.
// Phase 3 (last stats block): softplus/act/scalar combine + counter reset.
// ---------------------------------------------------------------------------
__global__ void k_fused(const float* __restrict__ sel_s,
                        const float* __restrict__ ker_s,
                        const float* __restrict__ sel_l,
                        const float* __restrict__ ker_l,
                        const float* __restrict__ fk,
                        const int* __restrict__ idx_s,
                        const int* __restrict__ idx_l,
                        float* __restrict__ out) {
    __shared__ float sa[CC];
    int lb = blockIdx.y;   // l*B + b
    int l  = lb / BB;
    int scale = (blockIdx.x >= NBS) ? 1 : 0;
    int bx = scale ? (blockIdx.x - NBS) : blockIdx.x;
    int N = scale ? NL : NS;
    const float* sel = scale ? sel_l : sel_s;
    const float* ker = scale ? ker_l : ker_s;

    // --- side duty: f_k mask sampling, duplicated per l band (idempotent) ---
    {
        int band_bid = (lb % BB) * GDX + blockIdx.x;   // 0..663 within band
        int s = band_bid * SAMP_PER_BLK + threadIdx.x;
        if (threadIdx.x < SAMP_PER_BLK && s < NSAMP) {
            if (s < BB*VS) {
                int b = s / VS, p = s % VS;
                int i = p / GS, j = p % GS;
                g_valid_s[s] = fk[(size_t)b*HH*WW + (size_t)i*8*WW + j*8] > 0.f;
            } else {
                int u = s - BB*VS;
                int b = u / VL, p = u % VL;
                int i = p / GL, j = p % GL;
                g_valid_l[u] = fk[(size_t)b*HH*WW + (size_t)i*28*WW + j*28] > 0.f;
            }
        }
    }

    // --- phase 1: distance rows (2 rows per warp, R9 config) ---
    const float* a = ker + (size_t)lb * CC;   // kernel (L,B,C,1) -> contiguous C
    for (int i = threadIdx.x; i < CC; i += blockDim.x) sa[i] = a[i];
    __syncthreads();

    {
        int warp = threadIdx.x >> 5;
        int lane = threadIdx.x & 31;
        int n0 = bx * ROWS_PER_BLK + warp;
        int n1 = n0 + 8;

        const float4* av = (const float4*)sa;
        float4 aa[CC/128];
#pragma unroll
        for (int k = 0; k < CC/128; k++) aa[k] = av[k*32 + lane];

        const float4* row0 = (const float4*)(sel + ((size_t)lb * N + n0) * CC);
        const float4* row1 = (const float4*)(sel + ((size_t)lb * N + n1) * CC);

        float s2a = 0.f, saba = 0.f;
        float s2b = 0.f, sabb = 0.f;
#pragma unroll
        for (int k = 0; k < CC/128; k++) {
            float4 v0 = row0[k*32 + lane];
            float4 v1 = row1[k*32 + lane];
            float4 A  = aa[k];
            float d0 = A.x - v0.x, d1 = A.y - v0.y, d2 = A.z - v0.z, d3 = A.w - v0.w;
            s2a = fmaf(d0, d0, s2a); s2a = fmaf(d1, d1, s2a);
            s2a = fmaf(d2, d2, s2a); s2a = fmaf(d3, d3, s2a);
            saba += fabsf(v0.x) + fabsf(v0.y) + fabsf(v0.z) + fabsf(v0.w);
            float e0 = A.x - v1.x, e1 = A.y - v1.y, e2 = A.z - v1.z, e3 = A.w - v1.w;
            s2b = fmaf(e0, e0, s2b); s2b = fmaf(e1, e1, s2b);
            s2b = fmaf(e2, e2, s2b); s2b = fmaf(e3, e3, s2b);
            sabb += fabsf(v1.x) + fabsf(v1.y) + fabsf(v1.z) + fabsf(v1.w);
        }
#pragma unroll
        for (int o = 16; o; o >>= 1) {
            s2a  += __shfl_xor_sync(0xFFFFFFFFu, s2a,  o);
            saba += __shfl_xor_sync(0xFFFFFFFFu, saba, o);
            s2b  += __shfl_xor_sync(0xFFFFFFFFu, s2b,  o);
            sabb += __shfl_xor_sync(0xFFFFFFFFu, sabb, o);
        }
        if (lane == 0) {
            int b = lb % BB;
            if (scale == 0) {
                g_dist_s[(size_t)lb * NS + n0] = sqrtf(s2a);
                g_dist_s[(size_t)lb * NS + n1] = sqrtf(s2b);
                g_nz_s[((size_t)l*NS + n0)*8 + b] = (saba != 0.f) ? 1 : 0;
                g_nz_s[((size_t)l*NS + n1)*8 + b] = (sabb != 0.f) ? 1 : 0;
            } else {
                g_dist_l[(size_t)lb * NL + n0] = sqrtf(s2a);
                g_dist_l[(size_t)lb * NL + n1] = sqrtf(s2b);
                g_nz_l[((size_t)l*NL + n0)*8 + b] = (saba != 0.f) ? 1 : 0;
                g_nz_l[((size_t)l*NL + n1)*8 + b] = (sabb != 0.f) ? 1 : 0;
            }
        }
    }

    // --- per-l ticket: last 16 finishers of this l band do its stats ---
    __shared__ unsigned s_ticket;
    __syncthreads();
    if (threadIdx.x == 0) {
        __threadfence();                       // publish dist/nz/valid writes
        s_ticket = atomicAdd(&g_cnt[l], 1u);
    }
    __syncthreads();
    if (s_ticket < BAND - 16) return;
    int slot = (int)(s_ticket - (BAND - 16));  // 0..15
    int sc2 = slot / BB;                       // 0 = s, 1 = l
    int b2  = slot % BB;
    int gb  = sc2 * LB + l * BB + b2;

    // wait for this l band only (other bands keep computing — overlap)
    if (threadIdx.x == 0) {
        while (atomicAdd(&g_cnt[l], 0u) < BAND) { }
    }
    __syncthreads();
    __threadfence();                           // acquire band's phase-1 writes

    // --- phase 2: masked accumulation for gb (MLP-5 gather) ---
    {
        int lb2 = l * BB + b2;
        int N2 = sc2 ? NL : NS;
        int V2 = sc2 ? VL : VS;
        const float* dist = sc2 ? g_dist_l : g_dist_s;
        const unsigned char* nzp = sc2 ? g_nz_l : g_nz_s;
        const unsigned char* valid = sc2 ? g_valid_l : g_valid_s;
        const int* idx = sc2 ? idx_l : idx_s;

        unsigned long long w[5];
        int   id[5];
        float d [5];
#pragma unroll
        for (int k = 0; k < 5; k++) {
            int n = k * 256 + threadIdx.x;
            bool ok = n < N2;
            w[k]  = ok ? *(const unsigned long long*)(nzp + ((size_t)l*N2 + n)*8) : 0ull;
            id[k] = ok ? idx[((size_t)l*BB + b2)*N2 + n] : 0;
            d[k]  = ok ? dist[(size_t)lb2*N2 + n] : 0.f;
        }

        float sp = 0.f, sn = 0.f;
        int   cp = 0,   cn = 0;
#pragma unroll
        for (int k = 0; k < 5; k++) {
            if (w[k] != 0ull) {
                bool mem = valid[b2*V2 + id[k]] != 0;
                if (mem) { sp += d[k]; cp++; } else { sn += d[k]; cn++; }
            }
        }

#pragma unroll
        for (int o = 16; o; o >>= 1) {
            sp += __shfl_xor_sync(0xFFFFFFFFu, sp, o);
            sn += __shfl_xor_sync(0xFFFFFFFFu, sn, o);
            cp += __shfl_xor_sync(0xFFFFFFFFu, cp, o);
            cn += __shfl_xor_sync(0xFFFFFFFFu, cn, o);
        }
        __shared__ float rsp[8], rsn[8];
        __shared__ int   rcp[8], rcn[8];
        int warp = threadIdx.x >> 5;
        if ((threadIdx.x & 31) == 0) { rsp[warp]=sp; rsn[warp]=sn; rcp[warp]=cp; rcn[warp]=cn; }
        __syncthreads();
        if (threadIdx.x == 0) {
            float tsp = 0.f, tsn = 0.f; int tcp = 0, tcn = 0;
#pragma unroll
            for (int v2 = 0; v2 < 8; v2++) {
                tsp += rsp[v2]; tsn += rsn[v2]; tcp += rcp[v2]; tcn += rcn[v2];
            }
            g_sp[gb] = tsp; g_sn[gb] = tsn; g_cp[gb] = tcp; g_cn[gb] = tcn;
        }
    }

    // --- phase 3: last stats block finalizes ---
    __shared__ bool is_last;
    __syncthreads();
    if (threadIdx.x == 0) {
        __threadfence();
        unsigned prev2 = atomicAdd(&g_done2, 1u);
        is_last = (prev2 == NGB - 1);
    }
    __syncthreads();
    if (!is_last) return;
    __threadfence();

    __shared__ float s_loss[NGB];
    __shared__ int   s_act [NGB];
    int t = threadIdx.x;
    if (t < NGB) {
        int tcp = g_cp[t], tcn = g_cn[t];
        float ap = g_sp[t] / (float)(tcp > 1 ? tcp : 1);
        float an = g_sn[t] / (float)(tcn > 1 ? tcn : 1);
        float x = ap - an;
        float loss = (x > 0.f) ? (x + log1pf(expf(-x))) : log1pf(expf(x));
        s_loss[t] = loss;
        s_act[t]  = (tcp > 0 && tcn > 0) ? 1 : 0;
    }
    __syncthreads();
    if (t < 64) {
        float v = 0.f; int c = 0;
        if (t < LB) {                       // small scale: act_s
            if (s_act[t]) { v = s_loss[t]; c = 1; }
        } else {                            // large scale: act_l & act_s
            if (s_act[t] && s_act[t - LB]) { v = s_loss[t]; c = 1; }
        }
#pragma unroll
        for (int o = 16; o; o >>= 1) {
            v += __shfl_xor_sync(0xFFFFFFFFu, v, o);
            c += __shfl_xor_sync(0xFFFFFFFFu, c, o);
        }
        __shared__ float sv[2]; __shared__ int sc3[2];
        int w2 = t >> 5;
        if ((t & 31) == 0) { sv[w2] = v; sc3[w2] = c; }
        __syncthreads();
        if (t == 0) {
            float total = sv[0] + sv[1];
            int times = sc3[0] + sc3[1];
            out[0] = (times > 0) ? total / (float)times : 0.f;
            // reset counters for the next (graph-replayed) invocation
            __threadfence();
            g_cnt[0] = 0u; g_cnt[1] = 0u; g_cnt[2] = 0u; g_cnt[3] = 0u;
            g_done2 = 0u;
        }
    }
}

// ---------------------------------------------------------------------------
extern "C" void kernel_launch(void* const* d_in, const int* in_sizes, int n_in,
                              void* d_out, int out_size) {
    const float* sel_s = (const float*)d_in[0];
    const int*   idx_s = (const int*)  d_in[1];
    const float* sel_l = (const float*)d_in[2];
    const int*   idx_l = (const int*)  d_in[3];
    const float* ker_s = (const float*)d_in[4];
    const float* ker_l = (const float*)d_in[5];
    const float* fk    = (const float*)d_in[6];

    dim3 gd(GDX, LB);   // (83, 32) = 2656 blocks
    k_fused<<<gd, 256>>>(sel_s, ker_s, sel_l, ker_l, fk,
                         idx_s, idx_l, (float*)d_out);
}

// round 12
// speedup vs baseline: 1.1308x; 1.1308x over previous
#include <cuda_runtime.h>
#include <math.h>

// Problem constants (fixed shapes from setup_inputs)
#define LL 4
#define BB 8
#define NS 1200
#define NL 128
#define CC 768
#define HH 448
#define WW 448
#define GS 56            // H/8   (grid cols, small)
#define GL 16            // H/28  (grid cols, large)
#define LB (LL*BB)       // 32
#define ROWS_PER_BLK 16          // 8 warps x 2 rows (best k_dist config)
#define NBS (NS/ROWS_PER_BLK)    // 75  (exact)
#define NBL (NL/ROWS_PER_BLK)    // 8   (exact)
#define GDX (NBS+NBL)            // 83
#define STATS_BLOCKS (2*LB)      // 64

// Scratch (no allocations -> __device__ globals). Device-code refs only.
// distm: distance with member flag in the sign bit (dist >= 0 always).
__device__ unsigned g_distm_s[LB*NS];
__device__ unsigned g_distm_l[LB*NL];
__device__ unsigned char g_nz_s[LL*NS*8];   // [l][n][b] nonzero flags
__device__ unsigned char g_nz_l[LL*NL*8];
__device__ float g_sp[2*LB];
__device__ float g_sn[2*LB];
__device__ int   g_cp[2*LB];
__device__ int   g_cn[2*LB];
__device__ unsigned g_done;

// ---------------------------------------------------------------------------
// 1) Main HBM-bound pass (both scales, one launch).
//    2 rows per warp, streaming float4 loads (__ldcs), anchor in registers.
//    Lane 0 prefetches idx + fk membership gather at block start (latency
//    hidden under the DRAM-bound main loop); member goes into the sign bit.
// ---------------------------------------------------------------------------
__global__ void k_dist(const float* __restrict__ sel_s,
                       const float* __restrict__ ker_s,
                       const float* __restrict__ sel_l,
                       const float* __restrict__ ker_l,
                       const float* __restrict__ fk,
                       const int* __restrict__ idx_s,
                       const int* __restrict__ idx_l) {
    __shared__ float sa[CC];
    int lb = blockIdx.y;   // l*B + b
    int l  = lb / BB;
    int b  = lb % BB;
    int scale = (blockIdx.x >= NBS) ? 1 : 0;
    int bx = scale ? (blockIdx.x - NBS) : blockIdx.x;
    int N = scale ? NL : NS;
    const float* sel = scale ? sel_l : sel_s;
    const float* ker = scale ? ker_l : ker_s;
    const int*   idx = scale ? idx_l : idx_s;

    int warp = threadIdx.x >> 5;
    int lane = threadIdx.x & 31;
    int n0 = bx * ROWS_PER_BLK + warp;   // rows n0 and n0+8 (no tail: exact)
    int n1 = n0 + 8;

    // --- membership prefetch (lane 0): idx -> fk gather, ~500cyc, hidden ---
    bool m0 = false, m1 = false;
    if (lane == 0) {
        int G = scale ? GL : GS;
        int S = scale ? 28 : 8;
        int id0 = idx[(size_t)lb * N + n0];
        int id1 = idx[(size_t)lb * N + n1];
        int gi0 = id0 / G, gj0 = id0 % G;
        int gi1 = id1 / G, gj1 = id1 % G;
        m0 = fk[(size_t)b*HH*WW + (size_t)gi0*S*WW + gj0*S] > 0.f;
        m1 = fk[(size_t)b*HH*WW + (size_t)gi1*S*WW + gj1*S] > 0.f;
    }

    // done-counter reset for k_stats (any single thread; consumed next kernel)
    if (blockIdx.x == 0 && blockIdx.y == 0 && threadIdx.x == 32) g_done = 0u;

    // anchor -> smem -> registers
    const float* a = ker + (size_t)lb * CC;   // kernel (L,B,C,1) -> contiguous C
    for (int i = threadIdx.x; i < CC; i += blockDim.x) sa[i] = a[i];
    __syncthreads();

    const float4* av = (const float4*)sa;
    float4 aa[CC/128];
#pragma unroll
    for (int k = 0; k < CC/128; k++) aa[k] = av[k*32 + lane];

    const float4* row0 = (const float4*)(sel + ((size_t)lb * N + n0) * CC);
    const float4* row1 = (const float4*)(sel + ((size_t)lb * N + n1) * CC);

    float s2a = 0.f, saba = 0.f;
    float s2b = 0.f, sabb = 0.f;
#pragma unroll
    for (int k = 0; k < CC/128; k++) {   // 6 iterations, 2x32 float4 each
        float4 v0 = __ldcs(&row0[k*32 + lane]);   // streaming: no reuse
        float4 v1 = __ldcs(&row1[k*32 + lane]);
        float4 A  = aa[k];
        float d0 = A.x - v0.x, d1 = A.y - v0.y, d2 = A.z - v0.z, d3 = A.w - v0.w;
        s2a = fmaf(d0, d0, s2a); s2a = fmaf(d1, d1, s2a);
        s2a = fmaf(d2, d2, s2a); s2a = fmaf(d3, d3, s2a);
        saba += fabsf(v0.x) + fabsf(v0.y) + fabsf(v0.z) + fabsf(v0.w);
        float e0 = A.x - v1.x, e1 = A.y - v1.y, e2 = A.z - v1.z, e3 = A.w - v1.w;
        s2b = fmaf(e0, e0, s2b); s2b = fmaf(e1, e1, s2b);
        s2b = fmaf(e2, e2, s2b); s2b = fmaf(e3, e3, s2b);
        sabb += fabsf(v1.x) + fabsf(v1.y) + fabsf(v1.z) + fabsf(v1.w);
    }
#pragma unroll
    for (int o = 16; o; o >>= 1) {
        s2a  += __shfl_xor_sync(0xFFFFFFFFu, s2a,  o);
        saba += __shfl_xor_sync(0xFFFFFFFFu, saba, o);
        s2b  += __shfl_xor_sync(0xFFFFFFFFu, s2b,  o);
        sabb += __shfl_xor_sync(0xFFFFFFFFu, sabb, o);
    }
    if (lane == 0) {
        unsigned u0 = __float_as_uint(sqrtf(s2a)) | (m0 ? 0x80000000u : 0u);
        unsigned u1 = __float_as_uint(sqrtf(s2b)) | (m1 ? 0x80000000u : 0u);
        if (scale == 0) {
            g_distm_s[(size_t)lb * NS + n0] = u0;
            g_distm_s[(size_t)lb * NS + n1] = u1;
            g_nz_s[((size_t)l*NS + n0)*8 + b] = (saba != 0.f) ? 1 : 0;
            g_nz_s[((size_t)l*NS + n1)*8 + b] = (sabb != 0.f) ? 1 : 0;
        } else {
            g_distm_l[(size_t)lb * NL + n0] = u0;
            g_distm_l[(size_t)lb * NL + n1] = u1;
            g_nz_l[((size_t)l*NL + n0)*8 + b] = (saba != 0.f) ? 1 : 0;
            g_nz_l[((size_t)l*NL + n1)*8 + b] = (sabb != 0.f) ? 1 : 0;
        }
    }
}

// ---------------------------------------------------------------------------
// 2) Stats: pure coalesced L2-hot reads (nz word + signed dist), no gathers.
//    One block per gb (64 blocks), deterministic reduce, last-block finalize.
// ---------------------------------------------------------------------------
__global__ void k_stats(float* __restrict__ out) {
    int gb = blockIdx.x;
    int scale = gb / LB;      // 0 = s, 1 = l
    int lb = gb % LB;
    int l = lb / BB;
    int N = scale ? NL : NS;
    const unsigned* distm = scale ? g_distm_l : g_distm_s;
    const unsigned char* nz = scale ? g_nz_l : g_nz_s;

    unsigned long long w[5];
    unsigned dm[5];
#pragma unroll
    for (int k = 0; k < 5; k++) {
        int n = k * 256 + threadIdx.x;
        bool ok = n < N;
        w[k]  = ok ? *(const unsigned long long*)(nz + ((size_t)l*N + n)*8) : 0ull;
        dm[k] = ok ? distm[(size_t)lb*N + n] : 0u;
    }

    float sp = 0.f, sn = 0.f;
    int   cp = 0,   cn = 0;
#pragma unroll
    for (int k = 0; k < 5; k++) {
        if (w[k] != 0ull) {
            float d = __uint_as_float(dm[k] & 0x7FFFFFFFu);
            if (dm[k] & 0x80000000u) { sp += d; cp++; } else { sn += d; cn++; }
        }
    }

#pragma unroll
    for (int o = 16; o; o >>= 1) {
        sp += __shfl_xor_sync(0xFFFFFFFFu, sp, o);
        sn += __shfl_xor_sync(0xFFFFFFFFu, sn, o);
        cp += __shfl_xor_sync(0xFFFFFFFFu, cp, o);
        cn += __shfl_xor_sync(0xFFFFFFFFu, cn, o);
    }
    __shared__ float rsp[8], rsn[8];
    __shared__ int   rcp[8], rcn[8];
    int warp = threadIdx.x >> 5;
    if ((threadIdx.x & 31) == 0) { rsp[warp]=sp; rsn[warp]=sn; rcp[warp]=cp; rcn[warp]=cn; }
    __syncthreads();
    if (threadIdx.x == 0) {
        float tsp = 0.f, tsn = 0.f; int tcp = 0, tcn = 0;
#pragma unroll
        for (int v2 = 0; v2 < 8; v2++) {
            tsp += rsp[v2]; tsn += rsn[v2]; tcp += rcp[v2]; tcn += rcn[v2];
        }
        g_sp[gb] = tsp; g_sn[gb] = tsn; g_cp[gb] = tcp; g_cn[gb] = tcn;
    }

    // ---- last-block finalization ----
    __shared__ bool is_last;
    __syncthreads();
    if (threadIdx.x == 0) {
        __threadfence();
        unsigned prev = atomicAdd(&g_done, 1u);
        is_last = (prev == STATS_BLOCKS - 1);
    }
    __syncthreads();
    if (!is_last) return;
    __threadfence();

    __shared__ float s_loss[2*LB];
    __shared__ int   s_act [2*LB];
    int t = threadIdx.x;
    if (t < 2*LB) {
        int tcp = g_cp[t], tcn = g_cn[t];
        float ap = g_sp[t] / (float)(tcp > 1 ? tcp : 1);
        float an = g_sn[t] / (float)(tcn > 1 ? tcn : 1);
        float x = ap - an;
        float loss = (x > 0.f) ? (x + log1pf(expf(-x))) : log1pf(expf(x));
        s_loss[t] = loss;
        s_act[t]  = (tcp > 0 && tcn > 0) ? 1 : 0;
    }
    __syncthreads();
    if (t < 64) {
        float v = 0.f; int c = 0;
        if (t < LB) {                       // small scale: act_s
            if (s_act[t]) { v = s_loss[t]; c = 1; }
        } else {                            // large scale: act_l & act_s
            if (s_act[t] && s_act[t - LB]) { v = s_loss[t]; c = 1; }
        }
#pragma unroll
        for (int o = 16; o; o >>= 1) {
            v += __shfl_xor_sync(0xFFFFFFFFu, v, o);
            c += __shfl_xor_sync(0xFFFFFFFFu, c, o);
        }
        __shared__ float sv[2]; __shared__ int sc[2];
        int w2 = t >> 5;
        if ((t & 31) == 0) { sv[w2] = v; sc[w2] = c; }
        __syncthreads();
        if (t == 0) {
            float total = sv[0] + sv[1];
            int times = sc[0] + sc[1];
            out[0] = (times > 0) ? total / (float)times : 0.f;
        }
    }
}

// ---------------------------------------------------------------------------
extern "C" void kernel_launch(void* const* d_in, const int* in_sizes, int n_in,
                              void* d_out, int out_size) {
    const float* sel_s = (const float*)d_in[0];
    const int*   idx_s = (const int*)  d_in[1];
    const float* sel_l = (const float*)d_in[2];
    const int*   idx_l = (const int*)  d_in[3];
    const float* ker_s = (const float*)d_in[4];
    const float* ker_l = (const float*)d_in[5];
    const float* fk    = (const float*)d_in[6];

    dim3 gd(GDX, LB);   // (83, 32) = 2656 blocks
    k_dist<<<gd, 256>>>(sel_s, ker_s, sel_l, ker_l, fk, idx_s, idx_l);

    k_stats<<<STATS_BLOCKS, 256>>>((float*)d_out);
}